// round 2
// baseline (speedup 1.0000x reference)
#include <cuda_runtime.h>
#include <math.h>
#include <stdint.h>

// Problem constants
#define Tn 512
#define Bn 8
#define En 1024
#define Hn 1024
#define Dn 512
#define Vn 32000
#define MROWS (Tn * Bn)   // 4096, row index m = b*Tn + t

// ---------------- scratch (device globals; no allocations allowed) ----------
__device__ float g_X[MROWS * En];       // embedded inputs, row m = b*T+t
__device__ float g_R0pre[MROWS * Dn];   // x @ Win0^T
__device__ float g_R1pre[MROWS * Dn];   // x @ Win1^T
__device__ float g_R0[MROWS * Dn];      // reservoir-0 trajectory
__device__ float g_R1[MROWS * Dn];      // reservoir-1 trajectory
__device__ float g_Hpre[MROWS * Hn];    // x@W_x^T + b_h (+ r@U^T later)
__device__ float g_H[MROWS * Hn];       // hidden trajectory
__device__ unsigned g_cnt[4];           // grid barriers (zero-init)
__device__ unsigned g_done[4];          // barrier reset counters

// ---------------- embedding gather ------------------------------------------
__global__ void embed_kernel(const int* __restrict__ ids,
                             const float* __restrict__ emb)
{
    int m = blockIdx.x;                       // m = b*T + t == flat index of ids[B][T]
    int id = __ldg(ids + m);
    float4 v = __ldg(((const float4*)(emb + (size_t)id * En)) + threadIdx.x);
    ((float4*)(g_X + (size_t)m * En))[threadIdx.x] = v;
}

// ---------------- generic NT SGEMM: C[m][n] (+)= A[m,:]·W[n,:] (+bias[n]) ----
// A: [M,K] row-major, W: [N,K] row-major. flags: 1=add bias, 2=accumulate into C.
// grid = (M/128, N/128), block = 256. M%128==0, N%128==0, K%16==0 assumed.
__global__ void __launch_bounds__(256)
sgemm_nt(const float* __restrict__ A, const float* __restrict__ W,
         const float* __restrict__ bias, float* __restrict__ C,
         int M, int N, int K, int flags)
{
    __shared__ __align__(16) float As[16][128];
    __shared__ __align__(16) float Ws[16][128];

    int bm0 = blockIdx.x * 128;
    int bn0 = blockIdx.y * 128;
    int tid = threadIdx.x;
    int tx = tid & 15, ty = tid >> 4;

    const float* Aptr = A + (size_t)bm0 * K;
    const float* Wptr = W + (size_t)bn0 * K;

    // each thread loads 2 float4 per tile for A and for W
    int q0 = tid, q1 = tid + 256;
    int r0 = q0 >> 2, kq0 = (q0 & 3) << 2;
    int r1 = q1 >> 2, kq1 = (q1 & 3) << 2;

    float4 ra0 = *(const float4*)(Aptr + (size_t)r0 * K + kq0);
    float4 ra1 = *(const float4*)(Aptr + (size_t)r1 * K + kq1);
    float4 rw0 = *(const float4*)(Wptr + (size_t)r0 * K + kq0);
    float4 rw1 = *(const float4*)(Wptr + (size_t)r1 * K + kq1);

    float acc[8][8];
#pragma unroll
    for (int i = 0; i < 8; i++)
#pragma unroll
        for (int j = 0; j < 8; j++) acc[i][j] = 0.f;

    for (int k0 = 0; k0 < K; k0 += 16) {
        As[kq0 + 0][r0] = ra0.x; As[kq0 + 1][r0] = ra0.y;
        As[kq0 + 2][r0] = ra0.z; As[kq0 + 3][r0] = ra0.w;
        As[kq1 + 0][r1] = ra1.x; As[kq1 + 1][r1] = ra1.y;
        As[kq1 + 2][r1] = ra1.z; As[kq1 + 3][r1] = ra1.w;
        Ws[kq0 + 0][r0] = rw0.x; Ws[kq0 + 1][r0] = rw0.y;
        Ws[kq0 + 2][r0] = rw0.z; Ws[kq0 + 3][r0] = rw0.w;
        Ws[kq1 + 0][r1] = rw1.x; Ws[kq1 + 1][r1] = rw1.y;
        Ws[kq1 + 2][r1] = rw1.z; Ws[kq1 + 3][r1] = rw1.w;
        __syncthreads();

        if (k0 + 16 < K) {   // prefetch next tile into regs; latency hidden by compute
            const float* An = Aptr + k0 + 16;
            const float* Wn = Wptr + k0 + 16;
            ra0 = *(const float4*)(An + (size_t)r0 * K + kq0);
            ra1 = *(const float4*)(An + (size_t)r1 * K + kq1);
            rw0 = *(const float4*)(Wn + (size_t)r0 * K + kq0);
            rw1 = *(const float4*)(Wn + (size_t)r1 * K + kq1);
        }

#pragma unroll
        for (int kk = 0; kk < 16; kk++) {
            float a[8], b[8];
            *(float4*)&a[0] = *(const float4*)&As[kk][ty * 8];
            *(float4*)&a[4] = *(const float4*)&As[kk][ty * 8 + 4];
            *(float4*)&b[0] = *(const float4*)&Ws[kk][tx * 8];
            *(float4*)&b[4] = *(const float4*)&Ws[kk][tx * 8 + 4];
#pragma unroll
            for (int i = 0; i < 8; i++)
#pragma unroll
                for (int j = 0; j < 8; j++) acc[i][j] += a[i] * b[j];
        }
        __syncthreads();
    }

    // epilogue
#pragma unroll
    for (int i = 0; i < 8; i++) {
        int m = bm0 + ty * 8 + i;
        float* crow = C + (size_t)m * N + bn0 + tx * 8;
#pragma unroll
        for (int jj = 0; jj < 8; jj += 4) {
            float4 v = make_float4(acc[i][jj], acc[i][jj + 1], acc[i][jj + 2], acc[i][jj + 3]);
            if (flags & 1) {
                int n = bn0 + tx * 8 + jj;
                v.x += __ldg(bias + n + 0); v.y += __ldg(bias + n + 1);
                v.z += __ldg(bias + n + 2); v.w += __ldg(bias + n + 3);
            }
            if (flags & 2) {
                float4 o = *(const float4*)(crow + jj);
                v.x += o.x; v.y += o.y; v.z += o.z; v.w += o.w;
            }
            *(float4*)(crow + jj) = v;
        }
    }
}

// ---------------- grid barrier helpers ---------------------------------------
__device__ __forceinline__ void gbar_arrive_wait(unsigned* cnt, unsigned target)
{
    // caller guarantees __threadfence + __syncthreads before this (writes visible)
    if (threadIdx.x == 0) {
        atomicAdd(cnt, 1u);
        while (*(volatile unsigned*)cnt < target) __nanosleep(32);
        __threadfence();
    }
    __syncthreads();
}

__device__ __forceinline__ void gbar_reset(unsigned* cnt, unsigned* done, unsigned nctas)
{
    // after ALL CTAs have passed the FINAL barrier (so nobody still spins on cnt)
    if (threadIdx.x == 0) {
        unsigned v = atomicAdd(done, 1u);
        if (v == nctas - 1u) { *done = 0u; *cnt = 0u; __threadfence(); }
    }
}

// ---------------- reservoir scans (both reservoirs, 64 CTAs each) -----------
// r_t = 0.5*r_{t-1} + 0.5*tanh(pre_t + r_{t-1} @ Wres^T)
__global__ void __launch_bounds__(256)
rscan_kernel(const float* __restrict__ pre0, const float* __restrict__ pre1,
             const float* __restrict__ W0, const float* __restrict__ W1,
             float* __restrict__ R0, float* __restrict__ R1)
{
    __shared__ __align__(16) float sW[8 * Dn];   // 8 Wres rows for this CTA
    __shared__ __align__(16) float sR[Bn * Dn];  // r_{t-1}, [b][d]

    int res  = blockIdx.x >> 6;        // 0 or 1
    int jblk = blockIdx.x & 63;
    int j0   = jblk * 8;
    const float* pre  = res ? pre1 : pre0;
    const float* Wres = res ? W1 : W0;
    float* Rout = res ? R1 : R0;
    unsigned* cnt = &g_cnt[res];

    int tid = threadIdx.x, lane = tid & 31, b = tid >> 5;   // warp == batch index

    for (int i = tid; i < 8 * Dn / 4; i += 256)
        ((float4*)sW)[i] = ((const float4*)(Wres + (size_t)j0 * Dn))[i];
    __syncthreads();

    for (int t = 0; t < Tn; ++t) {
        if (t == 0) {
            float4 z = make_float4(0.f, 0.f, 0.f, 0.f);
            for (int i = tid; i < Bn * Dn / 4; i += 256) ((float4*)sR)[i] = z;
        } else {
            for (int i = tid; i < Bn * Dn / 4; i += 256) {
                int bb = i >> 7, c = i & 127;   // 128 float4 per row
                ((float4*)sR)[i] =
                    __ldcg(((const float4*)(Rout + ((size_t)bb * Tn + (t - 1)) * Dn)) + c);
            }
        }
        __syncthreads();

        const float4* rb = (const float4*)(sR + b * Dn);
        float4 rv[4];
#pragma unroll
        for (int i = 0; i < 4; i++) rv[i] = rb[i * 32 + lane];

        float myout = 0.f;
#pragma unroll
        for (int jj = 0; jj < 8; ++jj) {
            const float4* wr = (const float4*)(sW + jj * Dn);
            float s = 0.f;
#pragma unroll
            for (int i = 0; i < 4; i++) {
                float4 w4 = wr[i * 32 + lane];
                s += rv[i].x * w4.x + rv[i].y * w4.y + rv[i].z * w4.z + rv[i].w * w4.w;
            }
#pragma unroll
            for (int off = 16; off; off >>= 1) s += __shfl_xor_sync(0xffffffffu, s, off);
            if (lane == jj) myout = s;
        }
        if (lane < 8) {
            int j = j0 + lane;
            size_t row = (size_t)b * Tn + t;
            float rold = sR[b * Dn + j];
            float p = __ldcg(pre + row * Dn + j);
            Rout[row * Dn + j] = 0.5f * rold + 0.5f * tanhf(p + myout);
        }
        __threadfence();
        __syncthreads();
        gbar_arrive_wait(cnt, 64u * (unsigned)(t + 1));
    }
    gbar_reset(cnt, &g_done[res], 64u);
}

// ---------------- hidden scan: h_t = tanh(Hpre_t + h_{t-1} @ W_h^T) ----------
__global__ void __launch_bounds__(256)
hscan_kernel(const float* __restrict__ Hpre, const float* __restrict__ Wh,
             float* __restrict__ Hout)
{
    extern __shared__ __align__(16) float smem[];
    float* sW = smem;            // 8 * 1024
    float* sH = smem + 8 * Hn;   // 8 * 1024

    int tid = threadIdx.x, lane = tid & 31, b = tid >> 5;
    int j0 = blockIdx.x * 8;
    unsigned* cnt = &g_cnt[2];

    for (int i = tid; i < 8 * Hn / 4; i += 256)
        ((float4*)sW)[i] = ((const float4*)(Wh + (size_t)j0 * Hn))[i];
    __syncthreads();

    for (int t = 0; t < Tn; ++t) {
        if (t == 0) {
            float4 z = make_float4(0.f, 0.f, 0.f, 0.f);
            for (int i = tid; i < Bn * Hn / 4; i += 256) ((float4*)sH)[i] = z;
        } else {
            for (int i = tid; i < Bn * Hn / 4; i += 256) {
                int bb = i >> 8, c = i & 255;   // 256 float4 per row
                ((float4*)sH)[i] =
                    __ldcg(((const float4*)(Hout + ((size_t)bb * Tn + (t - 1)) * Hn)) + c);
            }
        }
        __syncthreads();

        const float4* hb = (const float4*)(sH + b * Hn);
        float4 hv[8];
#pragma unroll
        for (int i = 0; i < 8; i++) hv[i] = hb[i * 32 + lane];

        float myout = 0.f;
#pragma unroll
        for (int jj = 0; jj < 8; ++jj) {
            const float4* wr = (const float4*)(sW + jj * Hn);
            float s = 0.f;
#pragma unroll
            for (int i = 0; i < 8; i++) {
                float4 w4 = wr[i * 32 + lane];
                s += hv[i].x * w4.x + hv[i].y * w4.y + hv[i].z * w4.z + hv[i].w * w4.w;
            }
#pragma unroll
            for (int off = 16; off; off >>= 1) s += __shfl_xor_sync(0xffffffffu, s, off);
            if (lane == jj) myout = s;
        }
        if (lane < 8) {
            int j = j0 + lane;
            size_t row = (size_t)b * Tn + t;
            float p = __ldcg(Hpre + row * Hn + j);
            Hout[row * Hn + j] = tanhf(p + myout);
        }
        __threadfence();
        __syncthreads();
        gbar_arrive_wait(cnt, 128u * (unsigned)(t + 1));
    }
    gbar_reset(cnt, &g_done[2], 128u);
}

// ---------------- launch ------------------------------------------------------
extern "C" void kernel_launch(void* const* d_in, const int* in_sizes, int n_in,
                              void* d_out, int out_size)
{
    const int*   ids   = (const int*)  d_in[0];
    const float* emb   = (const float*)d_in[1];
    const float* W_x   = (const float*)d_in[2];
    const float* W_h   = (const float*)d_in[3];
    const float* b_h   = (const float*)d_in[4];
    const float* Win0  = (const float*)d_in[5];
    const float* Wres0 = (const float*)d_in[6];
    const float* U0    = (const float*)d_in[7];
    const float* Win1  = (const float*)d_in[8];
    const float* Wres1 = (const float*)d_in[9];
    const float* U1    = (const float*)d_in[10];
    const float* outW  = (const float*)d_in[11];
    const float* outb  = (const float*)d_in[12];
    float* out = (float*)d_out;

    float *X, *R0pre, *R1pre, *R0, *R1, *Hpre, *Hst;
    cudaGetSymbolAddress((void**)&X,     g_X);
    cudaGetSymbolAddress((void**)&R0pre, g_R0pre);
    cudaGetSymbolAddress((void**)&R1pre, g_R1pre);
    cudaGetSymbolAddress((void**)&R0,    g_R0);
    cudaGetSymbolAddress((void**)&R1,    g_R1);
    cudaGetSymbolAddress((void**)&Hpre,  g_Hpre);
    cudaGetSymbolAddress((void**)&Hst,   g_H);

    cudaFuncSetAttribute(hscan_kernel,
                         cudaFuncAttributeMaxDynamicSharedMemorySize, 65536);

    // 1) embedding gather: X[m] = emb[ids[m]], m = b*T+t
    embed_kernel<<<MROWS, 256>>>(ids, emb);

    // 2) input projections (parallel over all t)
    sgemm_nt<<<dim3(MROWS / 128, Dn / 128), 256>>>(X, Win0, nullptr, R0pre, MROWS, Dn, En, 0);
    sgemm_nt<<<dim3(MROWS / 128, Dn / 128), 256>>>(X, Win1, nullptr, R1pre, MROWS, Dn, En, 0);
    sgemm_nt<<<dim3(MROWS / 128, Hn / 128), 256>>>(X, W_x,  b_h,     Hpre,  MROWS, Hn, En, 1);

    // 3) sequential reservoir scans (both reservoirs concurrently)
    rscan_kernel<<<128, 256>>>(R0pre, R1pre, Wres0, Wres1, R0, R1);

    // 4) reservoir -> hidden projections (parallel, accumulate into Hpre)
    sgemm_nt<<<dim3(MROWS / 128, Hn / 128), 256>>>(R0, U0, nullptr, Hpre, MROWS, Hn, Dn, 2);
    sgemm_nt<<<dim3(MROWS / 128, Hn / 128), 256>>>(R1, U1, nullptr, Hpre, MROWS, Hn, Dn, 2);

    // 5) sequential hidden scan
    hscan_kernel<<<128, 256, 65536>>>(Hpre, W_h, Hst);

    // 6) logits GEMM + bias (dominant cost)
    sgemm_nt<<<dim3(MROWS / 128, Vn / 128), 256>>>(Hst, outW, outb, out, MROWS, Vn, En, 1);
}

// round 4
// speedup vs baseline: 1.7574x; 1.7574x over previous
#include <cuda_runtime.h>
#include <cuda_bf16.h>
#include <math.h>
#include <stdint.h>

// Problem constants
#define Tn 512
#define Bn 8
#define En 1024
#define Hn 1024
#define Dn 512
#define Vn 32000
#define MROWS (Tn * Bn)   // 4096, row index m = b*Tn + t

// ---------------- scratch (device globals; no allocations allowed) ----------
__device__ float g_X[MROWS * En];
__device__ float g_R0pre[MROWS * Dn];
__device__ float g_R1pre[MROWS * Dn];
__device__ float g_R0[MROWS * Dn];
__device__ float g_R1[MROWS * Dn];
__device__ float g_Hpre[MROWS * Hn];
__device__ float g_H[MROWS * Hn];
__device__ unsigned g_cnt[4];
__device__ unsigned g_done[4];

// bf16 hi/lo split operands for the tensor-core logits GEMM
__device__ __nv_bfloat16 g_Whi[(size_t)Vn * Hn];
__device__ __nv_bfloat16 g_Wlo[(size_t)Vn * Hn];
__device__ __nv_bfloat16 g_Hhi[(size_t)MROWS * Hn];
__device__ __nv_bfloat16 g_Hlo[(size_t)MROWS * Hn];

// ================= portable PTX helpers (sm_80+) ============================
__device__ __forceinline__ uint32_t smem_u32(const void* p) {
    uint32_t a;
    asm("{ .reg .u64 t; cvta.to.shared.u64 t, %1; cvt.u32.u64 %0, t; }" : "=r"(a) : "l"(p));
    return a;
}
__device__ __forceinline__ void cp_async16(uint32_t saddr, const void* gaddr) {
    asm volatile("cp.async.cg.shared.global [%0], [%1], 16;" :: "r"(saddr), "l"(gaddr));
}
#define CP_COMMIT() asm volatile("cp.async.commit_group;" ::: "memory")
#define CP_WAIT(N)  asm volatile("cp.async.wait_group %0;" :: "n"(N) : "memory")

__device__ __forceinline__ void ldsm_x4(uint32_t& r0, uint32_t& r1, uint32_t& r2,
                                        uint32_t& r3, uint32_t addr) {
    asm volatile("ldmatrix.sync.aligned.m8n8.x4.shared.b16 {%0,%1,%2,%3}, [%4];"
                 : "=r"(r0), "=r"(r1), "=r"(r2), "=r"(r3) : "r"(addr));
}
__device__ __forceinline__ void mma16816(float* c, const uint32_t* a, const uint32_t* b) {
    asm volatile(
        "mma.sync.aligned.m16n8k16.row.col.f32.bf16.bf16.f32 "
        "{%0,%1,%2,%3}, {%4,%5,%6,%7}, {%8,%9}, {%0,%1,%2,%3};"
        : "+f"(c[0]), "+f"(c[1]), "+f"(c[2]), "+f"(c[3])
        : "r"(a[0]), "r"(a[1]), "r"(a[2]), "r"(a[3]), "r"(b[0]), "r"(b[1]));
}

// ---------------- embedding gather ------------------------------------------
__global__ void embed_kernel(const int* __restrict__ ids,
                             const float* __restrict__ emb)
{
    int m = blockIdx.x;
    int id = __ldg(ids + m);
    float4 v = __ldg(((const float4*)(emb + (size_t)id * En)) + threadIdx.x);
    ((float4*)(g_X + (size_t)m * En))[threadIdx.x] = v;
}

// ---------------- fp32 -> bf16 hi/lo split conversion ------------------------
__global__ void cvt_hilo_kernel(const float* __restrict__ src,
                                __nv_bfloat16* __restrict__ hi,
                                __nv_bfloat16* __restrict__ lo, int n4)
{
    int i = blockIdx.x * blockDim.x + threadIdx.x;
    if (i >= n4) return;
    float4 v = ((const float4*)src)[i];
    __nv_bfloat16 h0 = __float2bfloat16(v.x);
    __nv_bfloat16 h1 = __float2bfloat16(v.y);
    __nv_bfloat16 h2 = __float2bfloat16(v.z);
    __nv_bfloat16 h3 = __float2bfloat16(v.w);
    __nv_bfloat16 l0 = __float2bfloat16(v.x - __bfloat162float(h0));
    __nv_bfloat16 l1 = __float2bfloat16(v.y - __bfloat162float(h1));
    __nv_bfloat16 l2 = __float2bfloat16(v.z - __bfloat162float(h2));
    __nv_bfloat16 l3 = __float2bfloat16(v.w - __bfloat162float(h3));
    __nv_bfloat162* hp = (__nv_bfloat162*)hi;
    __nv_bfloat162* lp = (__nv_bfloat162*)lo;
    hp[i * 2 + 0] = __nv_bfloat162(h0, h1);
    hp[i * 2 + 1] = __nv_bfloat162(h2, h3);
    lp[i * 2 + 0] = __nv_bfloat162(l0, l1);
    lp[i * 2 + 1] = __nv_bfloat162(l2, l3);
}

// ---------------- logits GEMM on mma.sync (split-bf16, 3 terms) --------------
// C[m][n] = sum_k H[m][k]*W[n][k] + bias[n].
// CTA tile 128x128, K-chunk 64, 2-stage cp.async pipeline, SW128 swizzle.
// 8 warps as 2(m) x 4(n); warp tile 64x32; mma.m16n8k16 row.col bf16.
#define KCHUNK 64
#define TILEB (128 * KCHUNK * 2)          // 16384 bytes per operand tile
#define STAGEB (4 * TILEB)                // Ahi, Alo, Bhi, Blo

__global__ void __launch_bounds__(256, 1)
logits_mma(const __nv_bfloat16* __restrict__ Ahi, const __nv_bfloat16* __restrict__ Alo,
           const __nv_bfloat16* __restrict__ Bhi, const __nv_bfloat16* __restrict__ Blo,
           const float* __restrict__ bias, float* __restrict__ C)
{
    extern __shared__ __align__(16) char sm[];
    uint32_t sbase = smem_u32(sm);

    int tid = threadIdx.x, lane = tid & 31, wid = tid >> 5;
    int wm = wid >> 2, wn = wid & 3;              // 2 x 4 warp grid
    int m0 = blockIdx.x * 128, n0 = blockIdx.y * 128;

    const __nv_bfloat16* gsrc[4] = {
        Ahi + (size_t)m0 * En, Alo + (size_t)m0 * En,
        Bhi + (size_t)n0 * En, Blo + (size_t)n0 * En };

    // per-thread load pattern: chunk q = tid + i*256; r = q>>3 (row), c = q&7 (16B col)
    float acc[4][4][4];
#pragma unroll
    for (int a = 0; a < 4; a++)
#pragma unroll
        for (int b = 0; b < 4; b++)
#pragma unroll
            for (int cxx = 0; cxx < 4; cxx++) acc[a][b][cxx] = 0.f;

    // -------- stage issue helper (cp.async) --------
    auto issue_stage = [&](int s, int kc) {
        uint32_t stb = sbase + s * STAGEB;
#pragma unroll
        for (int t = 0; t < 4; ++t) {
            const __nv_bfloat16* g = gsrc[t] + kc * KCHUNK;
            uint32_t tb = stb + t * TILEB;
#pragma unroll
            for (int i = 0; i < 4; ++i) {
                int q = tid + i * 256;
                int r = q >> 3, c = q & 7;
                uint32_t sa = tb + ((r >> 3) << 10) + ((r & 7) << 7) + ((c ^ (r & 7)) << 4);
                cp_async16(sa, g + (size_t)r * En + c * 8);
            }
        }
    };

    issue_stage(0, 0);
    CP_COMMIT();

    const int NKC = En / KCHUNK;   // 16
    for (int kc = 0; kc < NKC; ++kc) {
        if (kc + 1 < NKC) {
            issue_stage((kc + 1) & 1, kc + 1);
            CP_COMMIT();
            CP_WAIT(1);
        } else {
            CP_WAIT(0);
        }
        __syncthreads();

        uint32_t sAh = sbase + (kc & 1) * STAGEB;
        uint32_t sAl = sAh + TILEB;
        uint32_t sBh = sAh + 2 * TILEB;
        uint32_t sBl = sAh + 3 * TILEB;

#pragma unroll
        for (int ks = 0; ks < KCHUNK / 16; ++ks) {   // 4 k16 substeps
            uint32_t ah[4][4], al[4][4], bh[4][2], bl[4][2];

            // A fragments: groups g0:m0-7@k0 g1:m8-15@k0 g2:m0-7@k8 g3:m8-15@k8
            int ra = (lane & 7) + ((lane >> 3) & 1) * 8;
            int ca = ks * 2 + ((lane >> 4) & 1);
#pragma unroll
            for (int mt = 0; mt < 4; ++mt) {
                int row = wm * 64 + mt * 16 + ra;
                uint32_t off = ((row >> 3) << 10) + ((row & 7) << 7)
                             + (((ca ^ (row & 7)) & 7) << 4);
                ldsm_x4(ah[mt][0], ah[mt][1], ah[mt][2], ah[mt][3], sAh + off);
                ldsm_x4(al[mt][0], al[mt][1], al[mt][2], al[mt][3], sAl + off);
            }
            // B fragments: groups g0:n0-7@k0 g1:n0-7@k8 g2:n8-15@k0 g3:n8-15@k8
            int rb = (lane & 7) + ((lane >> 4) & 1) * 8;
            int cb = ks * 2 + ((lane >> 3) & 1);
#pragma unroll
            for (int np = 0; np < 2; ++np) {
                int row = wn * 32 + np * 16 + rb;
                uint32_t off = ((row >> 3) << 10) + ((row & 7) << 7)
                             + (((cb ^ (row & 7)) & 7) << 4);
                ldsm_x4(bh[np * 2][0], bh[np * 2][1],
                        bh[np * 2 + 1][0], bh[np * 2 + 1][1], sBh + off);
                ldsm_x4(bl[np * 2][0], bl[np * 2][1],
                        bl[np * 2 + 1][0], bl[np * 2 + 1][1], sBl + off);
            }

#pragma unroll
            for (int mt = 0; mt < 4; ++mt)
#pragma unroll
                for (int nt = 0; nt < 4; ++nt) {
                    mma16816(acc[mt][nt], ah[mt], bh[nt]);   // hi*hi
                    mma16816(acc[mt][nt], ah[mt], bl[nt]);   // hi*lo
                    mma16816(acc[mt][nt], al[mt], bh[nt]);   // lo*hi
                }
        }
        __syncthreads();
    }

    // -------- epilogue: add bias, store fp32 --------
#pragma unroll
    for (int mt = 0; mt < 4; ++mt) {
        int r0 = m0 + wm * 64 + mt * 16 + (lane >> 2);
#pragma unroll
        for (int nt = 0; nt < 4; ++nt) {
            int cc = n0 + wn * 32 + nt * 8 + (lane & 3) * 2;
            float2 bia = *(const float2*)(bias + cc);
            float2 v0 = make_float2(acc[mt][nt][0] + bia.x, acc[mt][nt][1] + bia.y);
            float2 v1 = make_float2(acc[mt][nt][2] + bia.x, acc[mt][nt][3] + bia.y);
            *(float2*)(C + (size_t)r0 * Vn + cc) = v0;
            *(float2*)(C + (size_t)(r0 + 8) * Vn + cc) = v1;
        }
    }
}

// ---------------- generic NT SGEMM (fp32, small GEMMs) -----------------------
__global__ void __launch_bounds__(256)
sgemm_nt(const float* __restrict__ A, const float* __restrict__ W,
         const float* __restrict__ bias, float* __restrict__ C,
         int M, int N, int K, int flags)
{
    __shared__ __align__(16) float As[16][128];
    __shared__ __align__(16) float Ws[16][128];

    int bm0 = blockIdx.x * 128;
    int bn0 = blockIdx.y * 128;
    int tid = threadIdx.x;
    int tx = tid & 15, ty = tid >> 4;

    const float* Aptr = A + (size_t)bm0 * K;
    const float* Wptr = W + (size_t)bn0 * K;

    int q0 = tid, q1 = tid + 256;
    int r0 = q0 >> 2, kq0 = (q0 & 3) << 2;
    int r1 = q1 >> 2, kq1 = (q1 & 3) << 2;

    float4 ra0 = *(const float4*)(Aptr + (size_t)r0 * K + kq0);
    float4 ra1 = *(const float4*)(Aptr + (size_t)r1 * K + kq1);
    float4 rw0 = *(const float4*)(Wptr + (size_t)r0 * K + kq0);
    float4 rw1 = *(const float4*)(Wptr + (size_t)r1 * K + kq1);

    float acc[8][8];
#pragma unroll
    for (int i = 0; i < 8; i++)
#pragma unroll
        for (int j = 0; j < 8; j++) acc[i][j] = 0.f;

    for (int k0 = 0; k0 < K; k0 += 16) {
        As[kq0 + 0][r0] = ra0.x; As[kq0 + 1][r0] = ra0.y;
        As[kq0 + 2][r0] = ra0.z; As[kq0 + 3][r0] = ra0.w;
        As[kq1 + 0][r1] = ra1.x; As[kq1 + 1][r1] = ra1.y;
        As[kq1 + 2][r1] = ra1.z; As[kq1 + 3][r1] = ra1.w;
        Ws[kq0 + 0][r0] = rw0.x; Ws[kq0 + 1][r0] = rw0.y;
        Ws[kq0 + 2][r0] = rw0.z; Ws[kq0 + 3][r0] = rw0.w;
        Ws[kq1 + 0][r1] = rw1.x; Ws[kq1 + 1][r1] = rw1.y;
        Ws[kq1 + 2][r1] = rw1.z; Ws[kq1 + 3][r1] = rw1.w;
        __syncthreads();

        if (k0 + 16 < K) {
            const float* An = Aptr + k0 + 16;
            const float* Wn = Wptr + k0 + 16;
            ra0 = *(const float4*)(An + (size_t)r0 * K + kq0);
            ra1 = *(const float4*)(An + (size_t)r1 * K + kq1);
            rw0 = *(const float4*)(Wn + (size_t)r0 * K + kq0);
            rw1 = *(const float4*)(Wn + (size_t)r1 * K + kq1);
        }

#pragma unroll
        for (int kk = 0; kk < 16; kk++) {
            float a[8], b[8];
            *(float4*)&a[0] = *(const float4*)&As[kk][ty * 8];
            *(float4*)&a[4] = *(const float4*)&As[kk][ty * 8 + 4];
            *(float4*)&b[0] = *(const float4*)&Ws[kk][tx * 8];
            *(float4*)&b[4] = *(const float4*)&Ws[kk][tx * 8 + 4];
#pragma unroll
            for (int i = 0; i < 8; i++)
#pragma unroll
                for (int j = 0; j < 8; j++) acc[i][j] += a[i] * b[j];
        }
        __syncthreads();
    }

#pragma unroll
    for (int i = 0; i < 8; i++) {
        int m = bm0 + ty * 8 + i;
        float* crow = C + (size_t)m * N + bn0 + tx * 8;
#pragma unroll
        for (int jj = 0; jj < 8; jj += 4) {
            float4 v = make_float4(acc[i][jj], acc[i][jj + 1], acc[i][jj + 2], acc[i][jj + 3]);
            if (flags & 1) {
                int n = bn0 + tx * 8 + jj;
                v.x += __ldg(bias + n + 0); v.y += __ldg(bias + n + 1);
                v.z += __ldg(bias + n + 2); v.w += __ldg(bias + n + 3);
            }
            if (flags & 2) {
                float4 o = *(const float4*)(crow + jj);
                v.x += o.x; v.y += o.y; v.z += o.z; v.w += o.w;
            }
            *(float4*)(crow + jj) = v;
        }
    }
}

// ---------------- grid barrier helpers ---------------------------------------
__device__ __forceinline__ void gbar_arrive_wait(unsigned* cnt, unsigned target)
{
    if (threadIdx.x == 0) {
        atomicAdd(cnt, 1u);
        while (*(volatile unsigned*)cnt < target) __nanosleep(32);
        __threadfence();
    }
    __syncthreads();
}

__device__ __forceinline__ void gbar_reset(unsigned* cnt, unsigned* done, unsigned nctas)
{
    if (threadIdx.x == 0) {
        unsigned v = atomicAdd(done, 1u);
        if (v == nctas - 1u) { *done = 0u; *cnt = 0u; __threadfence(); }
    }
}

// ---------------- reservoir scans (both reservoirs, 64 CTAs each) -----------
__global__ void __launch_bounds__(256)
rscan_kernel(const float* __restrict__ pre0, const float* __restrict__ pre1,
             const float* __restrict__ W0, const float* __restrict__ W1,
             float* __restrict__ R0, float* __restrict__ R1)
{
    __shared__ __align__(16) float sW[8 * Dn];
    __shared__ __align__(16) float sR[Bn * Dn];

    int res  = blockIdx.x >> 6;
    int jblk = blockIdx.x & 63;
    int j0   = jblk * 8;
    const float* pre  = res ? pre1 : pre0;
    const float* Wres = res ? W1 : W0;
    float* Rout = res ? R1 : R0;
    unsigned* cnt = &g_cnt[res];

    int tid = threadIdx.x, lane = tid & 31, b = tid >> 5;

    for (int i = tid; i < 8 * Dn / 4; i += 256)
        ((float4*)sW)[i] = ((const float4*)(Wres + (size_t)j0 * Dn))[i];
    __syncthreads();

    for (int t = 0; t < Tn; ++t) {
        if (t == 0) {
            float4 z = make_float4(0.f, 0.f, 0.f, 0.f);
            for (int i = tid; i < Bn * Dn / 4; i += 256) ((float4*)sR)[i] = z;
        } else {
            for (int i = tid; i < Bn * Dn / 4; i += 256) {
                int bb = i >> 7, c = i & 127;
                ((float4*)sR)[i] =
                    __ldcg(((const float4*)(Rout + ((size_t)bb * Tn + (t - 1)) * Dn)) + c);
            }
        }
        __syncthreads();

        const float4* rb = (const float4*)(sR + b * Dn);
        float4 rv[4];
#pragma unroll
        for (int i = 0; i < 4; i++) rv[i] = rb[i * 32 + lane];

        float myout = 0.f;
#pragma unroll
        for (int jj = 0; jj < 8; ++jj) {
            const float4* wr = (const float4*)(sW + jj * Dn);
            float sv = 0.f;
#pragma unroll
            for (int i = 0; i < 4; i++) {
                float4 w4 = wr[i * 32 + lane];
                sv += rv[i].x * w4.x + rv[i].y * w4.y + rv[i].z * w4.z + rv[i].w * w4.w;
            }
#pragma unroll
            for (int off = 16; off; off >>= 1) sv += __shfl_xor_sync(0xffffffffu, sv, off);
            if (lane == jj) myout = sv;
        }
        if (lane < 8) {
            int j = j0 + lane;
            size_t row = (size_t)b * Tn + t;
            float rold = sR[b * Dn + j];
            float p = __ldcg(pre + row * Dn + j);
            Rout[row * Dn + j] = 0.5f * rold + 0.5f * tanhf(p + myout);
        }
        __threadfence();
        __syncthreads();
        gbar_arrive_wait(cnt, 64u * (unsigned)(t + 1));
    }
    gbar_reset(cnt, &g_done[res], 64u);
}

// ---------------- hidden scan -------------------------------------------------
__global__ void __launch_bounds__(256)
hscan_kernel(const float* __restrict__ Hpre, const float* __restrict__ Wh,
             float* __restrict__ Hout)
{
    extern __shared__ __align__(16) float smem[];
    float* sW = smem;
    float* sH = smem + 8 * Hn;

    int tid = threadIdx.x, lane = tid & 31, b = tid >> 5;
    int j0 = blockIdx.x * 8;
    unsigned* cnt = &g_cnt[2];

    for (int i = tid; i < 8 * Hn / 4; i += 256)
        ((float4*)sW)[i] = ((const float4*)(Wh + (size_t)j0 * Hn))[i];
    __syncthreads();

    for (int t = 0; t < Tn; ++t) {
        if (t == 0) {
            float4 z = make_float4(0.f, 0.f, 0.f, 0.f);
            for (int i = tid; i < Bn * Hn / 4; i += 256) ((float4*)sH)[i] = z;
        } else {
            for (int i = tid; i < Bn * Hn / 4; i += 256) {
                int bb = i >> 8, c = i & 255;
                ((float4*)sH)[i] =
                    __ldcg(((const float4*)(Hout + ((size_t)bb * Tn + (t - 1)) * Hn)) + c);
            }
        }
        __syncthreads();

        const float4* hb = (const float4*)(sH + b * Hn);
        float4 hv[8];
#pragma unroll
        for (int i = 0; i < 8; i++) hv[i] = hb[i * 32 + lane];

        float myout = 0.f;
#pragma unroll
        for (int jj = 0; jj < 8; ++jj) {
            const float4* wr = (const float4*)(sW + jj * Hn);
            float sv = 0.f;
#pragma unroll
            for (int i = 0; i < 8; i++) {
                float4 w4 = wr[i * 32 + lane];
                sv += hv[i].x * w4.x + hv[i].y * w4.y + hv[i].z * w4.z + hv[i].w * w4.w;
            }
#pragma unroll
            for (int off = 16; off; off >>= 1) sv += __shfl_xor_sync(0xffffffffu, sv, off);
            if (lane == jj) myout = sv;
        }
        if (lane < 8) {
            int j = j0 + lane;
            size_t row = (size_t)b * Tn + t;
            float p = __ldcg(Hpre + row * Hn + j);
            Hout[row * Hn + j] = tanhf(p + myout);
        }
        __threadfence();
        __syncthreads();
        gbar_arrive_wait(cnt, 128u * (unsigned)(t + 1));
    }
    gbar_reset(cnt, &g_done[2], 128u);
}

// ---------------- launch ------------------------------------------------------
extern "C" void kernel_launch(void* const* d_in, const int* in_sizes, int n_in,
                              void* d_out, int out_size)
{
    const int*   ids   = (const int*)  d_in[0];
    const float* emb   = (const float*)d_in[1];
    const float* W_x   = (const float*)d_in[2];
    const float* W_h   = (const float*)d_in[3];
    const float* b_h   = (const float*)d_in[4];
    const float* Win0  = (const float*)d_in[5];
    const float* Wres0 = (const float*)d_in[6];
    const float* U0    = (const float*)d_in[7];
    const float* Win1  = (const float*)d_in[8];
    const float* Wres1 = (const float*)d_in[9];
    const float* U1    = (const float*)d_in[10];
    const float* outW  = (const float*)d_in[11];
    const float* outb  = (const float*)d_in[12];
    float* out = (float*)d_out;

    float *X, *R0pre, *R1pre, *R0, *R1, *Hpre, *Hst;
    __nv_bfloat16 *Whi, *Wlo, *Hhi, *Hlo;
    cudaGetSymbolAddress((void**)&X,     g_X);
    cudaGetSymbolAddress((void**)&R0pre, g_R0pre);
    cudaGetSymbolAddress((void**)&R1pre, g_R1pre);
    cudaGetSymbolAddress((void**)&R0,    g_R0);
    cudaGetSymbolAddress((void**)&R1,    g_R1);
    cudaGetSymbolAddress((void**)&Hpre,  g_Hpre);
    cudaGetSymbolAddress((void**)&Hst,   g_H);
    cudaGetSymbolAddress((void**)&Whi,   g_Whi);
    cudaGetSymbolAddress((void**)&Wlo,   g_Wlo);
    cudaGetSymbolAddress((void**)&Hhi,   g_Hhi);
    cudaGetSymbolAddress((void**)&Hlo,   g_Hlo);

    cudaFuncSetAttribute(hscan_kernel,
                         cudaFuncAttributeMaxDynamicSharedMemorySize, 65536);
    cudaFuncSetAttribute(logits_mma,
                         cudaFuncAttributeMaxDynamicSharedMemorySize, 2 * STAGEB);

    // 1) embedding gather
    embed_kernel<<<MROWS, 256>>>(ids, emb);

    // 1b) out_W -> bf16 hi/lo (independent of everything else)
    cvt_hilo_kernel<<<(Vn * Hn / 4 + 255) / 256, 256>>>(outW, Whi, Wlo, Vn * Hn / 4);

    // 2) input projections
    sgemm_nt<<<dim3(MROWS / 128, Dn / 128), 256>>>(X, Win0, nullptr, R0pre, MROWS, Dn, En, 0);
    sgemm_nt<<<dim3(MROWS / 128, Dn / 128), 256>>>(X, Win1, nullptr, R1pre, MROWS, Dn, En, 0);
    sgemm_nt<<<dim3(MROWS / 128, Hn / 128), 256>>>(X, W_x,  b_h,     Hpre,  MROWS, Hn, En, 1);

    // 3) sequential reservoir scans
    rscan_kernel<<<128, 256>>>(R0pre, R1pre, Wres0, Wres1, R0, R1);

    // 4) reservoir -> hidden projections
    sgemm_nt<<<dim3(MROWS / 128, Hn / 128), 256>>>(R0, U0, nullptr, Hpre, MROWS, Hn, Dn, 2);
    sgemm_nt<<<dim3(MROWS / 128, Hn / 128), 256>>>(R1, U1, nullptr, Hpre, MROWS, Hn, Dn, 2);

    // 5) sequential hidden scan
    hscan_kernel<<<128, 256, 65536>>>(Hpre, W_h, Hst);

    // 5b) H -> bf16 hi/lo
    cvt_hilo_kernel<<<(MROWS * Hn / 4 + 255) / 256, 256>>>(Hst, Hhi, Hlo, MROWS * Hn / 4);

    // 6) logits GEMM + bias on mma.sync tensor cores (split-bf16, 3 terms)
    logits_mma<<<dim3(MROWS / 128, Vn / 128), 256, 2 * STAGEB>>>(
        Hhi, Hlo, Whi, Wlo, outb, out);
}

// round 5
// speedup vs baseline: 2.1120x; 1.2018x over previous
#include <cuda_runtime.h>
#include <cuda_bf16.h>
#include <cuda_fp16.h>
#include <math.h>
#include <stdint.h>

// Problem constants
#define Tn 512
#define Bn 8
#define En 1024
#define Hn 1024
#define Dn 512
#define Vn 32000
#define MROWS (Tn * Bn)   // 4096, row index m = b*Tn + t

// ---------------- scratch (device globals; no allocations allowed) ----------
__device__ float g_X[MROWS * En];
__device__ float g_R0pre[MROWS * Dn];
__device__ float g_R1pre[MROWS * Dn];
__device__ float g_R0[MROWS * Dn];
__device__ float g_R1[MROWS * Dn];
__device__ float g_Hpre[MROWS * Hn];
__device__ float g_H[MROWS * Hn];
__device__ unsigned g_cnt[4];
__device__ unsigned g_done[4];

// fp16 operands for the tensor-core logits GEMM (single-pass)
__device__ __half g_Wh[(size_t)Vn * Hn];
__device__ __half g_Hh[(size_t)MROWS * Hn];

// ================= portable PTX helpers (sm_80+) ============================
__device__ __forceinline__ uint32_t smem_u32(const void* p) {
    uint32_t a;
    asm("{ .reg .u64 t; cvta.to.shared.u64 t, %1; cvt.u32.u64 %0, t; }" : "=r"(a) : "l"(p));
    return a;
}
__device__ __forceinline__ void cp_async16(uint32_t saddr, const void* gaddr) {
    asm volatile("cp.async.cg.shared.global [%0], [%1], 16;" :: "r"(saddr), "l"(gaddr));
}
#define CP_COMMIT() asm volatile("cp.async.commit_group;" ::: "memory")
#define CP_WAIT(N)  asm volatile("cp.async.wait_group %0;" :: "n"(N) : "memory")

__device__ __forceinline__ void ldsm_x4(uint32_t& r0, uint32_t& r1, uint32_t& r2,
                                        uint32_t& r3, uint32_t addr) {
    asm volatile("ldmatrix.sync.aligned.m8n8.x4.shared.b16 {%0,%1,%2,%3}, [%4];"
                 : "=r"(r0), "=r"(r1), "=r"(r2), "=r"(r3) : "r"(addr));
}
__device__ __forceinline__ void mma16816h(float* c, const uint32_t* a, const uint32_t* b) {
    asm volatile(
        "mma.sync.aligned.m16n8k16.row.col.f32.f16.f16.f32 "
        "{%0,%1,%2,%3}, {%4,%5,%6,%7}, {%8,%9}, {%0,%1,%2,%3};"
        : "+f"(c[0]), "+f"(c[1]), "+f"(c[2]), "+f"(c[3])
        : "r"(a[0]), "r"(a[1]), "r"(a[2]), "r"(a[3]), "r"(b[0]), "r"(b[1]));
}

// ---------------- embedding gather ------------------------------------------
__global__ void embed_kernel(const int* __restrict__ ids,
                             const float* __restrict__ emb)
{
    int m = blockIdx.x;
    int id = __ldg(ids + m);
    float4 v = __ldg(((const float4*)(emb + (size_t)id * En)) + threadIdx.x);
    ((float4*)(g_X + (size_t)m * En))[threadIdx.x] = v;
}

// ---------------- fp32 -> fp16 conversion ------------------------------------
__global__ void cvt_h_kernel(const float* __restrict__ src,
                             __half* __restrict__ dst, int n4)
{
    int i = blockIdx.x * blockDim.x + threadIdx.x;
    if (i >= n4) return;
    float4 v = ((const float4*)src)[i];
    __half2* dp = (__half2*)dst;
    dp[i * 2 + 0] = __floats2half2_rn(v.x, v.y);
    dp[i * 2 + 1] = __floats2half2_rn(v.z, v.w);
}

// ---------------- logits GEMM on mma.sync (single-pass fp16) -----------------
// C[m][n] = sum_k H[m][k]*W[n][k] + bias[n].
// CTA tile 128x128, K-chunk 64, 2-stage cp.async pipeline, SW128 swizzle.
// 8 warps as 2(m) x 4(n); warp tile 64x32; 2 CTAs/SM for cross-CTA overlap.
#define KCHUNK 64
#define TILEB (128 * KCHUNK * 2)          // 16384 bytes per operand tile
#define STAGEB (2 * TILEB)                // A, B

__global__ void __launch_bounds__(256, 2)
logits_mma(const __half* __restrict__ A, const __half* __restrict__ B,
           const float* __restrict__ bias, float* __restrict__ C)
{
    extern __shared__ __align__(16) char sm[];
    uint32_t sbase = smem_u32(sm);

    int tid = threadIdx.x, lane = tid & 31, wid = tid >> 5;
    int wm = wid >> 2, wn = wid & 3;              // 2 x 4 warp grid
    int m0 = blockIdx.x * 128, n0 = blockIdx.y * 128;

    const __half* gA = A + (size_t)m0 * En;
    const __half* gB = B + (size_t)n0 * En;

    float acc[4][4][4];
#pragma unroll
    for (int a = 0; a < 4; a++)
#pragma unroll
        for (int b = 0; b < 4; b++)
#pragma unroll
            for (int cxx = 0; cxx < 4; cxx++) acc[a][b][cxx] = 0.f;

    // -------- stage issue helper (cp.async); tile geometry: 128 rows x 8 16B-chunks
    auto issue_stage = [&](int s, int kc) {
        uint32_t stb = sbase + s * STAGEB;
        const __half* gs[2] = { gA + kc * KCHUNK, gB + kc * KCHUNK };
#pragma unroll
        for (int t = 0; t < 2; ++t) {
            uint32_t tb = stb + t * TILEB;
#pragma unroll
            for (int i = 0; i < 4; ++i) {
                int q = tid + i * 256;
                int r = q >> 3, c = q & 7;
                uint32_t sa = tb + ((r >> 3) << 10) + ((r & 7) << 7) + ((c ^ (r & 7)) << 4);
                cp_async16(sa, gs[t] + (size_t)r * En + c * 8);
            }
        }
    };

    issue_stage(0, 0);
    CP_COMMIT();

    const int NKC = En / KCHUNK;   // 16
    for (int kc = 0; kc < NKC; ++kc) {
        if (kc + 1 < NKC) {
            issue_stage((kc + 1) & 1, kc + 1);
            CP_COMMIT();
            CP_WAIT(1);
        } else {
            CP_WAIT(0);
        }
        __syncthreads();

        uint32_t sA = sbase + (kc & 1) * STAGEB;
        uint32_t sB = sA + TILEB;

#pragma unroll
        for (int ks = 0; ks < KCHUNK / 16; ++ks) {   // 4 k16 substeps
            uint32_t ah[4][4], bh[4][2];

            // A fragments: groups g0:m0-7@k0 g1:m8-15@k0 g2:m0-7@k8 g3:m8-15@k8
            int ra = (lane & 7) + ((lane >> 3) & 1) * 8;
            int ca = ks * 2 + ((lane >> 4) & 1);
#pragma unroll
            for (int mt = 0; mt < 4; ++mt) {
                int row = wm * 64 + mt * 16 + ra;
                uint32_t off = ((row >> 3) << 10) + ((row & 7) << 7)
                             + (((ca ^ (row & 7)) & 7) << 4);
                ldsm_x4(ah[mt][0], ah[mt][1], ah[mt][2], ah[mt][3], sA + off);
            }
            // B fragments: groups g0:n0-7@k0 g1:n0-7@k8 g2:n8-15@k0 g3:n8-15@k8
            int rb = (lane & 7) + ((lane >> 4) & 1) * 8;
            int cb = ks * 2 + ((lane >> 3) & 1);
#pragma unroll
            for (int np = 0; np < 2; ++np) {
                int row = wn * 32 + np * 16 + rb;
                uint32_t off = ((row >> 3) << 10) + ((row & 7) << 7)
                             + (((cb ^ (row & 7)) & 7) << 4);
                ldsm_x4(bh[np * 2][0], bh[np * 2][1],
                        bh[np * 2 + 1][0], bh[np * 2 + 1][1], sB + off);
            }

#pragma unroll
            for (int mt = 0; mt < 4; ++mt)
#pragma unroll
                for (int nt = 0; nt < 4; ++nt)
                    mma16816h(acc[mt][nt], ah[mt], bh[nt]);
        }
        __syncthreads();
    }

    // -------- epilogue: add bias, store fp32 --------
#pragma unroll
    for (int mt = 0; mt < 4; ++mt) {
        int r0 = m0 + wm * 64 + mt * 16 + (lane >> 2);
#pragma unroll
        for (int nt = 0; nt < 4; ++nt) {
            int cc = n0 + wn * 32 + nt * 8 + (lane & 3) * 2;
            float2 bia = *(const float2*)(bias + cc);
            float2 v0 = make_float2(acc[mt][nt][0] + bia.x, acc[mt][nt][1] + bia.y);
            float2 v1 = make_float2(acc[mt][nt][2] + bia.x, acc[mt][nt][3] + bia.y);
            *(float2*)(C + (size_t)r0 * Vn + cc) = v0;
            *(float2*)(C + (size_t)(r0 + 8) * Vn + cc) = v1;
        }
    }
}

// ---------------- generic NT SGEMM (fp32, small GEMMs) -----------------------
__global__ void __launch_bounds__(256, 2)
sgemm_nt(const float* __restrict__ A, const float* __restrict__ W,
         const float* __restrict__ bias, float* __restrict__ C,
         int M, int N, int K, int flags)
{
    __shared__ __align__(16) float As[16][128];
    __shared__ __align__(16) float Ws[16][128];

    int bm0 = blockIdx.x * 128;
    int bn0 = blockIdx.y * 128;
    int tid = threadIdx.x;
    int tx = tid & 15, ty = tid >> 4;

    const float* Aptr = A + (size_t)bm0 * K;
    const float* Wptr = W + (size_t)bn0 * K;

    int q0 = tid, q1 = tid + 256;
    int r0 = q0 >> 2, kq0 = (q0 & 3) << 2;
    int r1 = q1 >> 2, kq1 = (q1 & 3) << 2;

    float4 ra0 = *(const float4*)(Aptr + (size_t)r0 * K + kq0);
    float4 ra1 = *(const float4*)(Aptr + (size_t)r1 * K + kq1);
    float4 rw0 = *(const float4*)(Wptr + (size_t)r0 * K + kq0);
    float4 rw1 = *(const float4*)(Wptr + (size_t)r1 * K + kq1);

    float acc[8][8];
#pragma unroll
    for (int i = 0; i < 8; i++)
#pragma unroll
        for (int j = 0; j < 8; j++) acc[i][j] = 0.f;

    for (int k0 = 0; k0 < K; k0 += 16) {
        As[kq0 + 0][r0] = ra0.x; As[kq0 + 1][r0] = ra0.y;
        As[kq0 + 2][r0] = ra0.z; As[kq0 + 3][r0] = ra0.w;
        As[kq1 + 0][r1] = ra1.x; As[kq1 + 1][r1] = ra1.y;
        As[kq1 + 2][r1] = ra1.z; As[kq1 + 3][r1] = ra1.w;
        Ws[kq0 + 0][r0] = rw0.x; Ws[kq0 + 1][r0] = rw0.y;
        Ws[kq0 + 2][r0] = rw0.z; Ws[kq0 + 3][r0] = rw0.w;
        Ws[kq1 + 0][r1] = rw1.x; Ws[kq1 + 1][r1] = rw1.y;
        Ws[kq1 + 2][r1] = rw1.z; Ws[kq1 + 3][r1] = rw1.w;
        __syncthreads();

        if (k0 + 16 < K) {
            const float* An = Aptr + k0 + 16;
            const float* Wn = Wptr + k0 + 16;
            ra0 = *(const float4*)(An + (size_t)r0 * K + kq0);
            ra1 = *(const float4*)(An + (size_t)r1 * K + kq1);
            rw0 = *(const float4*)(Wn + (size_t)r0 * K + kq0);
            rw1 = *(const float4*)(Wn + (size_t)r1 * K + kq1);
        }

#pragma unroll
        for (int kk = 0; kk < 16; kk++) {
            float a[8], b[8];
            *(float4*)&a[0] = *(const float4*)&As[kk][ty * 8];
            *(float4*)&a[4] = *(const float4*)&As[kk][ty * 8 + 4];
            *(float4*)&b[0] = *(const float4*)&Ws[kk][tx * 8];
            *(float4*)&b[4] = *(const float4*)&Ws[kk][tx * 8 + 4];
#pragma unroll
            for (int i = 0; i < 8; i++)
#pragma unroll
                for (int j = 0; j < 8; j++) acc[i][j] += a[i] * b[j];
        }
        __syncthreads();
    }

#pragma unroll
    for (int i = 0; i < 8; i++) {
        int m = bm0 + ty * 8 + i;
        float* crow = C + (size_t)m * N + bn0 + tx * 8;
#pragma unroll
        for (int jj = 0; jj < 8; jj += 4) {
            float4 v = make_float4(acc[i][jj], acc[i][jj + 1], acc[i][jj + 2], acc[i][jj + 3]);
            if (flags & 1) {
                int n = bn0 + tx * 8 + jj;
                v.x += __ldg(bias + n + 0); v.y += __ldg(bias + n + 1);
                v.z += __ldg(bias + n + 2); v.w += __ldg(bias + n + 3);
            }
            if (flags & 2) {
                float4 o = *(const float4*)(crow + jj);
                v.x += o.x; v.y += o.y; v.z += o.z; v.w += o.w;
            }
            *(float4*)(crow + jj) = v;
        }
    }
}

// ---------------- grid barrier helpers ---------------------------------------
// Caller guarantees __syncthreads() immediately before (CTA writes visible to
// thread 0 via bar.sync hb-edge); thread-0 fence is cumulative -> gpu scope.
__device__ __forceinline__ void gbar_arrive_wait(unsigned* cnt, unsigned target)
{
    if (threadIdx.x == 0) {
        __threadfence();
        atomicAdd(cnt, 1u);
        while (*(volatile unsigned*)cnt < target) __nanosleep(32);
        __threadfence();
    }
    __syncthreads();
}

__device__ __forceinline__ void gbar_reset(unsigned* cnt, unsigned* done, unsigned nctas)
{
    if (threadIdx.x == 0) {
        unsigned v = atomicAdd(done, 1u);
        if (v == nctas - 1u) { *done = 0u; *cnt = 0u; __threadfence(); }
    }
}

// ---------------- reservoir scans (both reservoirs, 64 CTAs each) -----------
__global__ void __launch_bounds__(256)
rscan_kernel(const float* __restrict__ pre0, const float* __restrict__ pre1,
             const float* __restrict__ W0, const float* __restrict__ W1,
             float* __restrict__ R0, float* __restrict__ R1)
{
    __shared__ __align__(16) float sW[8 * Dn];
    __shared__ __align__(16) float sR[Bn * Dn];

    int res  = blockIdx.x >> 6;
    int jblk = blockIdx.x & 63;
    int j0   = jblk * 8;
    const float* pre  = res ? pre1 : pre0;
    const float* Wres = res ? W1 : W0;
    float* Rout = res ? R1 : R0;
    unsigned* cnt = &g_cnt[res];

    int tid = threadIdx.x, lane = tid & 31, b = tid >> 5;

    for (int i = tid; i < 8 * Dn / 4; i += 256)
        ((float4*)sW)[i] = ((const float4*)(Wres + (size_t)j0 * Dn))[i];
    __syncthreads();

    for (int t = 0; t < Tn; ++t) {
        if (t == 0) {
            float4 z = make_float4(0.f, 0.f, 0.f, 0.f);
            for (int i = tid; i < Bn * Dn / 4; i += 256) ((float4*)sR)[i] = z;
        } else {
            for (int i = tid; i < Bn * Dn / 4; i += 256) {
                int bb = i >> 7, c = i & 127;
                ((float4*)sR)[i] =
                    __ldcg(((const float4*)(Rout + ((size_t)bb * Tn + (t - 1)) * Dn)) + c);
            }
        }
        __syncthreads();

        const float4* rb = (const float4*)(sR + b * Dn);
        float4 rv[4];
#pragma unroll
        for (int i = 0; i < 4; i++) rv[i] = rb[i * 32 + lane];

        float myout = 0.f;
#pragma unroll
        for (int jj = 0; jj < 8; ++jj) {
            const float4* wr = (const float4*)(sW + jj * Dn);
            float sv = 0.f;
#pragma unroll
            for (int i = 0; i < 4; i++) {
                float4 w4 = wr[i * 32 + lane];
                sv += rv[i].x * w4.x + rv[i].y * w4.y + rv[i].z * w4.z + rv[i].w * w4.w;
            }
#pragma unroll
            for (int off = 16; off; off >>= 1) sv += __shfl_xor_sync(0xffffffffu, sv, off);
            if (lane == jj) myout = sv;
        }
        if (lane < 8) {
            int j = j0 + lane;
            size_t row = (size_t)b * Tn + t;
            float rold = sR[b * Dn + j];
            float p = __ldcg(pre + row * Dn + j);
            Rout[row * Dn + j] = 0.5f * rold + 0.5f * tanhf(p + myout);
        }
        __syncthreads();
        gbar_arrive_wait(cnt, 64u * (unsigned)(t + 1));
    }
    gbar_reset(cnt, &g_done[res], 64u);
}

// ---------------- hidden scan -------------------------------------------------
__global__ void __launch_bounds__(256)
hscan_kernel(const float* __restrict__ Hpre, const float* __restrict__ Wh,
             float* __restrict__ Hout)
{
    extern __shared__ __align__(16) float smem[];
    float* sW = smem;
    float* sH = smem + 8 * Hn;

    int tid = threadIdx.x, lane = tid & 31, b = tid >> 5;
    int j0 = blockIdx.x * 8;
    unsigned* cnt = &g_cnt[2];

    for (int i = tid; i < 8 * Hn / 4; i += 256)
        ((float4*)sW)[i] = ((const float4*)(Wh + (size_t)j0 * Hn))[i];
    __syncthreads();

    for (int t = 0; t < Tn; ++t) {
        if (t == 0) {
            float4 z = make_float4(0.f, 0.f, 0.f, 0.f);
            for (int i = tid; i < Bn * Hn / 4; i += 256) ((float4*)sH)[i] = z;
        } else {
            for (int i = tid; i < Bn * Hn / 4; i += 256) {
                int bb = i >> 8, c = i & 255;
                ((float4*)sH)[i] =
                    __ldcg(((const float4*)(Hout + ((size_t)bb * Tn + (t - 1)) * Hn)) + c);
            }
        }
        __syncthreads();

        const float4* hb = (const float4*)(sH + b * Hn);
        float4 hv[8];
#pragma unroll
        for (int i = 0; i < 8; i++) hv[i] = hb[i * 32 + lane];

        float myout = 0.f;
#pragma unroll
        for (int jj = 0; jj < 8; ++jj) {
            const float4* wr = (const float4*)(sW + jj * Hn);
            float sv = 0.f;
#pragma unroll
            for (int i = 0; i < 8; i++) {
                float4 w4 = wr[i * 32 + lane];
                sv += hv[i].x * w4.x + hv[i].y * w4.y + hv[i].z * w4.z + hv[i].w * w4.w;
            }
#pragma unroll
            for (int off = 16; off; off >>= 1) sv += __shfl_xor_sync(0xffffffffu, sv, off);
            if (lane == jj) myout = sv;
        }
        if (lane < 8) {
            int j = j0 + lane;
            size_t row = (size_t)b * Tn + t;
            float p = __ldcg(Hpre + row * Hn + j);
            Hout[row * Hn + j] = tanhf(p + myout);
        }
        __syncthreads();
        gbar_arrive_wait(cnt, 128u * (unsigned)(t + 1));
    }
    gbar_reset(cnt, &g_done[2], 128u);
}

// ---------------- launch ------------------------------------------------------
extern "C" void kernel_launch(void* const* d_in, const int* in_sizes, int n_in,
                              void* d_out, int out_size)
{
    const int*   ids   = (const int*)  d_in[0];
    const float* emb   = (const float*)d_in[1];
    const float* W_x   = (const float*)d_in[2];
    const float* W_h   = (const float*)d_in[3];
    const float* b_h   = (const float*)d_in[4];
    const float* Win0  = (const float*)d_in[5];
    const float* Wres0 = (const float*)d_in[6];
    const float* U0    = (const float*)d_in[7];
    const float* Win1  = (const float*)d_in[8];
    const float* Wres1 = (const float*)d_in[9];
    const float* U1    = (const float*)d_in[10];
    const float* outW  = (const float*)d_in[11];
    const float* outb  = (const float*)d_in[12];
    float* out = (float*)d_out;

    float *X, *R0pre, *R1pre, *R0, *R1, *Hpre, *Hst;
    __half *Wh16, *Hh16;
    cudaGetSymbolAddress((void**)&X,     g_X);
    cudaGetSymbolAddress((void**)&R0pre, g_R0pre);
    cudaGetSymbolAddress((void**)&R1pre, g_R1pre);
    cudaGetSymbolAddress((void**)&R0,    g_R0);
    cudaGetSymbolAddress((void**)&R1,    g_R1);
    cudaGetSymbolAddress((void**)&Hpre,  g_Hpre);
    cudaGetSymbolAddress((void**)&Hst,   g_H);
    cudaGetSymbolAddress((void**)&Wh16,  g_Wh);
    cudaGetSymbolAddress((void**)&Hh16,  g_Hh);

    cudaFuncSetAttribute(hscan_kernel,
                         cudaFuncAttributeMaxDynamicSharedMemorySize, 65536);
    cudaFuncSetAttribute(logits_mma,
                         cudaFuncAttributeMaxDynamicSharedMemorySize, 2 * STAGEB);

    // 1) embedding gather
    embed_kernel<<<MROWS, 256>>>(ids, emb);

    // 1b) out_W -> fp16 (independent of everything else)
    cvt_h_kernel<<<(Vn * Hn / 4 + 255) / 256, 256>>>(outW, Wh16, Vn * Hn / 4);

    // 2) input projections
    sgemm_nt<<<dim3(MROWS / 128, Dn / 128), 256>>>(X, Win0, nullptr, R0pre, MROWS, Dn, En, 0);
    sgemm_nt<<<dim3(MROWS / 128, Dn / 128), 256>>>(X, Win1, nullptr, R1pre, MROWS, Dn, En, 0);
    sgemm_nt<<<dim3(MROWS / 128, Hn / 128), 256>>>(X, W_x,  b_h,     Hpre,  MROWS, Hn, En, 1);

    // 3) sequential reservoir scans
    rscan_kernel<<<128, 256>>>(R0pre, R1pre, Wres0, Wres1, R0, R1);

    // 4) reservoir -> hidden projections
    sgemm_nt<<<dim3(MROWS / 128, Hn / 128), 256>>>(R0, U0, nullptr, Hpre, MROWS, Hn, Dn, 2);
    sgemm_nt<<<dim3(MROWS / 128, Hn / 128), 256>>>(R1, U1, nullptr, Hpre, MROWS, Hn, Dn, 2);

    // 5) sequential hidden scan
    hscan_kernel<<<128, 256, 65536>>>(Hpre, W_h, Hst);

    // 5b) H -> fp16
    cvt_h_kernel<<<(MROWS * Hn / 4 + 255) / 256, 256>>>(Hst, Hh16, MROWS * Hn / 4);

    // 6) logits GEMM + bias on mma.sync tensor cores (single-pass fp16)
    logits_mma<<<dim3(MROWS / 128, Vn / 128), 256, 2 * STAGEB>>>(Hh16, Wh16, outb, out);
}